// round 4
// baseline (speedup 1.0000x reference)
#include <cuda_runtime.h>
#include <cooperative_groups.h>

namespace cg = cooperative_groups;

namespace {
constexpr int   kB       = 8;
constexpr int   kNT      = 256;
constexpr int   kNZ      = 256;
constexpr int   kNX      = 256;
constexpr int   kNREC    = 64;
constexpr int   kThreads = 512;               // 2 groups of 256 (column = tid & 255)
constexpr float kDT2     = 1.0e-6f;           // DT*DT
constexpr float kInvDH2  = 0.01f;             // 1/(DH*DH)

constexpr int smem_floats(int cluster) {
    int rows = kNZ / cluster;
    int bufFloats = rows * kNX;
    return 2 * bufFloats + kNT + 64 + 64 + 4;
}
// Pad to >114KB so at most ONE CTA fits per SM (228KB unified carveout):
// kills cross-cluster double-packing stragglers. We don't need L1D anyway.
constexpr int kSmemPad16 = 116736;            // bytes, > 228*1024/2
constexpr int smem_bytes(int cluster) {
    int natural = smem_floats(cluster) * 4;
    return (cluster == 16 && natural < kSmemPad16) ? kSmemPad16 : natural;
}
}

template <int CLUSTER>
__global__ void __launch_bounds__(kThreads, 1)
wave_fd_kernel(const float* __restrict__ x,
               const float* __restrict__ vp,
               const int*   __restrict__ src_loc,
               const int*   __restrict__ rec_loc,
               float*       __restrict__ out)
{
    constexpr int kRows = kNZ / CLUSTER;      // rows per CTA
    constexpr int kHalf = kRows / 2;          // rows per thread
    constexpr int kBufFloats = kRows * kNX;
    constexpr int kWavOff = 2 * kBufFloats;
    constexpr int kIntOff = kWavOff + kNT;

    extern __shared__ float sm[];
    float* bufA   = sm;
    float* bufB   = sm + kBufFloats;
    float* wav    = sm + kWavOff;
    int*   recOff = (int*)(sm + kIntOff);
    int*   recK   = recOff + 64;
    int*   recCnt = recK + 64;

    cg::cluster_group cluster = cg::this_cluster();
    const int rank  = (int)cluster.block_rank();
    const int batch = blockIdx.x / CLUSTER;
    const int tid   = threadIdx.x;
    const int c     = tid & (kNX - 1);        // column 0..255
    const int g     = tid >> 8;               // which half of the slab
    const int gz0   = rank * kRows + g * kHalf;

    // ---- init: zero ping-pong buffers, wavelet, receiver list ----
    for (int i = tid; i < 2 * kBufFloats; i += kThreads) sm[i] = 0.0f;
    if (tid < kNT) wav[tid] = x[batch * kNT + tid];
    if (tid == 0) *recCnt = 0;
    __syncthreads();
    if (tid < kNREC) {
        int rz = rec_loc[(batch * kNREC + tid) * 2 + 0];
        int rx = rec_loc[(batch * kNREC + tid) * 2 + 1];
        if (rz >= rank * kRows && rz < (rank + 1) * kRows) {
            int slot = atomicAdd(recCnt, 1);
            recOff[slot] = (rz - rank * kRows) * kNX + rx;
            recK[slot]   = tid;
        }
    }
    __syncthreads();
    const int cnt = *recCnt;

    // ---- source ownership ----
    const int  sz     = src_loc[batch * 2 + 0];
    const int  sx     = src_loc[batch * 2 + 1];
    const bool isSrc  = (c == sx) && (sz >= gz0) && (sz < gz0 + kHalf);
    const int  srcOff = (sz - rank * kRows) * kNX + c;

    // ---- per-cell coefficients and h^{t-1} in registers ----
    float c2[kHalf], h2[kHalf];
#pragma unroll
    for (int i = 0; i < kHalf; i++) {
        float v = vp[(gz0 + i) * kNX + c];
        c2[i] = v * v * kDT2;
        h2[i] = 0.0f;
    }

    const bool active    = (c > 0) && (c < kNX - 1);
    const bool skipFirst = (rank == 0) && (g == 0);            // global row 0
    const bool skipLast  = (rank == CLUSTER - 1) && (g == 1);  // global row NZ-1

    // ---- DSMEM neighbor pointers (clamped at cluster edges) ----
    const int prevRank = (rank == 0) ? 0 : rank - 1;
    const int nextRank = (rank == CLUSTER - 1) ? rank : rank + 1;
    const float* prevA = cluster.map_shared_rank(bufA, prevRank);
    const float* prevB = cluster.map_shared_rank(bufB, prevRank);
    const float* nextA = cluster.map_shared_rank(bufA, nextRank);
    const float* nextB = cluster.map_shared_rank(bufB, nextRank);

    cluster.sync();   // buffers zeroed everywhere before first halo read

    const int strip = g * kHalf * kNX + c;

    for (int t = 0; t < kNT; t++) {
        const float* cur     = (t & 1) ? bufB : bufA;
        float*       nxt     = (t & 1) ? bufA : bufB;
        const float* prevCur = (t & 1) ? prevB : prevA;
        const float* nextCur = (t & 1) ? nextB : nextA;

        if (active) {
            const float* cb = cur + strip;
            float*       nb = nxt + strip;

            // Remote (DSMEM) halo load issued first...
            float halo = (g == 0) ? prevCur[(kRows - 1) * kNX + c]
                                  : nextCur[c];

            if (g == 0) {
                // ...and consumed LAST: iterate rows bottom-up so the remote
                // row-above value is only needed at i=0, ~7 rows of work later.
                float cp1 = cb[kHalf * kNX];          // g=1's first row (local)
                float c0  = cb[(kHalf - 1) * kNX];
#pragma unroll
                for (int i = kHalf - 1; i >= 0; i--) {
                    float cm1 = (i > 0) ? cb[(i - 1) * kNX] : halo;
                    float l   = cb[i * kNX - 1];
                    float r   = cb[i * kNX + 1];
                    float lap = ((cm1 + cp1) + (l + r) - 4.0f * c0) * kInvDH2;
                    float hn  = fmaf(c2[i], lap, 2.0f * c0 - h2[i]);
                    h2[i] = c0;
                    if (!(i == 0 && skipFirst)) nb[i * kNX] = hn;
                    cp1 = c0; c0 = cm1;
                }
            } else {
                // g=1 iterates top-down; its remote halo (row below) is
                // already consumed at the last row.
                float cm1 = cb[-kNX];                 // g=0's last row (local)
                float c0  = cb[0];
#pragma unroll
                for (int i = 0; i < kHalf; i++) {
                    float cp1 = (i < kHalf - 1) ? cb[(i + 1) * kNX] : halo;
                    float l   = cb[i * kNX - 1];
                    float r   = cb[i * kNX + 1];
                    float lap = ((cm1 + cp1) + (l + r) - 4.0f * c0) * kInvDH2;
                    float hn  = fmaf(c2[i], lap, 2.0f * c0 - h2[i]);
                    h2[i] = c0;
                    if (!(i == kHalf - 1 && skipLast)) nb[i * kNX] = hn;
                    cm1 = c0; c0 = cp1;
                }
            }
            if (isSrc) nxt[srcOff] += kDT2 * wav[t];
        }

        cluster.sync();   // single barrier per step: nxt complete cluster-wide

        // gather AFTER the sync; this buffer is not rewritten until t+2,
        // which is ordered after sync(t+1) > this gather.
        if (tid < cnt)
            out[(batch * kNT + t) * kNREC + recK[tid]] = nxt[recOff[tid]];
    }
}

extern "C" void kernel_launch(void* const* d_in, const int* in_sizes, int n_in,
                              void* d_out, int out_size)
{
    (void)in_sizes; (void)n_in; (void)out_size;
    const float* x   = (const float*)d_in[0];
    const float* vp  = (const float*)d_in[1];
    const int*   src = (const int*)d_in[2];
    const int*   rec = (const int*)d_in[3];
    float*       out = (float*)d_out;

    cudaFuncSetAttribute(wave_fd_kernel<16>,
                         cudaFuncAttributeMaxDynamicSharedMemorySize, smem_bytes(16));
    cudaFuncSetAttribute(wave_fd_kernel<16>,
                         cudaFuncAttributeNonPortableClusterSizeAllowed, 1);
    cudaFuncSetAttribute(wave_fd_kernel<8>,
                         cudaFuncAttributeMaxDynamicSharedMemorySize, smem_bytes(8));

    int maxCluster = 0;
    {
        cudaLaunchConfig_t probe = {};
        probe.gridDim          = dim3(kB * 16, 1, 1);
        probe.blockDim         = dim3(kThreads, 1, 1);
        probe.dynamicSmemBytes = smem_bytes(16);
        cudaOccupancyMaxPotentialClusterSize(&maxCluster, (const void*)wave_fd_kernel<16>, &probe);
    }

    cudaLaunchAttribute attr[1];
    attr[0].id = cudaLaunchAttributeClusterDimension;
    attr[0].val.clusterDim.y = 1;
    attr[0].val.clusterDim.z = 1;

    cudaLaunchConfig_t cfg = {};
    cfg.blockDim = dim3(kThreads, 1, 1);
    cfg.stream   = 0;
    cfg.attrs    = attr;
    cfg.numAttrs = 1;

    if (maxCluster >= 16) {
        cfg.gridDim              = dim3(kB * 16, 1, 1);
        cfg.dynamicSmemBytes     = smem_bytes(16);
        attr[0].val.clusterDim.x = 16;
        cudaLaunchKernelEx(&cfg, wave_fd_kernel<16>, x, vp, src, rec, out);
    } else {
        cfg.gridDim              = dim3(kB * 8, 1, 1);
        cfg.dynamicSmemBytes     = smem_bytes(8);
        attr[0].val.clusterDim.x = 8;
        cudaLaunchKernelEx(&cfg, wave_fd_kernel<8>, x, vp, src, rec, out);
    }
}

// round 6
// speedup vs baseline: 1.5038x; 1.5038x over previous
#include <cuda_runtime.h>
#include <cooperative_groups.h>

namespace cg = cooperative_groups;

namespace {
constexpr int   kB       = 8;
constexpr int   kNT      = 256;
constexpr int   kNZ      = 256;
constexpr int   kNX      = 256;
constexpr int   kNREC    = 64;
constexpr int   kThreads = 512;               // 2 groups of 256 (column = tid & 255)
constexpr float kDT2     = 1.0e-6f;           // DT*DT
constexpr float kInvDH2  = 0.01f;             // 1/(DH*DH)

constexpr int smem_floats(int cluster) {
    int rows = kNZ / cluster;
    int bufFloats = rows * kNX;
    return 2 * bufFloats + kNT + 64 + 64 + 4;
}
constexpr int smem_bytes(int cluster) { return smem_floats(cluster) * 4; }
}

#define CLUSTER_ARRIVE() asm volatile("barrier.cluster.arrive.aligned;" ::: "memory")
#define CLUSTER_WAIT()   asm volatile("barrier.cluster.wait.aligned;"   ::: "memory")

template <int CLUSTER>
__global__ void __launch_bounds__(kThreads, 1)
wave_fd_kernel(const float* __restrict__ x,
               const float* __restrict__ vp,
               const int*   __restrict__ src_loc,
               const int*   __restrict__ rec_loc,
               float*       __restrict__ out)
{
    constexpr int kRows = kNZ / CLUSTER;      // rows per CTA
    constexpr int kHalf = kRows / 2;          // rows per thread
    constexpr int kBufFloats = kRows * kNX;
    constexpr int kWavOff = 2 * kBufFloats;
    constexpr int kIntOff = kWavOff + kNT;

    extern __shared__ float sm[];
    float* bufA   = sm;
    float* bufB   = sm + kBufFloats;
    float* wav    = sm + kWavOff;
    int*   recOff = (int*)(sm + kIntOff);
    int*   recK   = recOff + 64;
    int*   recCnt = recK + 64;

    cg::cluster_group cluster = cg::this_cluster();
    const int rank  = (int)cluster.block_rank();
    const int batch = blockIdx.x / CLUSTER;
    const int tid   = threadIdx.x;
    const int c     = tid & (kNX - 1);        // column 0..255
    const int g     = tid >> 8;               // which half of the slab
    const int gz0   = rank * kRows + g * kHalf;

    // ---- init: zero ping-pong buffers, wavelet, receiver list ----
    for (int i = tid; i < 2 * kBufFloats; i += kThreads) sm[i] = 0.0f;
    if (tid < kNT) wav[tid] = x[batch * kNT + tid];
    if (tid == 0) *recCnt = 0;
    __syncthreads();
    if (tid < kNREC) {
        int rz = rec_loc[(batch * kNREC + tid) * 2 + 0];
        int rx = rec_loc[(batch * kNREC + tid) * 2 + 1];
        if (rz >= rank * kRows && rz < (rank + 1) * kRows) {
            int slot = atomicAdd(recCnt, 1);
            recOff[slot] = (rz - rank * kRows) * kNX + rx;
            recK[slot]   = tid;
        }
    }
    __syncthreads();
    const int cnt = *recCnt;

    // ---- source ownership: row within this thread's half, column match ----
    const int  sz       = src_loc[batch * 2 + 0];
    const int  sx       = src_loc[batch * 2 + 1];
    const bool isSrcCol = (c == sx);
    const int  srcRow   = sz - gz0;           // 0..kHalf-1 if this thread's half

    // ---- per-cell coefficients and h^{t-1} in registers ----
    float c2[kHalf], h2[kHalf];
#pragma unroll
    for (int i = 0; i < kHalf; i++) {
        float v = vp[(gz0 + i) * kNX + c];
        c2[i] = v * v * kDT2;
        h2[i] = 0.0f;
    }

    const bool active    = (c > 0) && (c < kNX - 1);
    const bool skipFirst = (rank == 0) && (g == 0);            // global row 0
    const bool skipLast  = (rank == CLUSTER - 1) && (g == 1);  // global row NZ-1

    // ---- DSMEM neighbor pointers (clamped at cluster edges) ----
    const int prevRank = (rank == 0) ? 0 : rank - 1;
    const int nextRank = (rank == CLUSTER - 1) ? rank : rank + 1;
    const float* prevA = cluster.map_shared_rank(bufA, prevRank);
    const float* prevB = cluster.map_shared_rank(bufB, prevRank);
    const float* nextA = cluster.map_shared_rank(bufA, nextRank);
    const float* nextB = cluster.map_shared_rank(bufB, nextRank);

    cluster.sync();   // buffers zeroed everywhere before first halo read

    const int strip = g * kHalf * kNX + c;

    for (int t = 0; t < kNT; t++) {
        const float* cur     = (t & 1) ? bufB : bufA;
        float*       nxt     = (t & 1) ? bufA : bufB;
        const float* prevCur = (t & 1) ? prevB : prevA;
        const float* nextCur = (t & 1) ? nextB : nextA;

        const float* cb = cur + strip;
        float*       nb = nxt + strip;
        const float  inj = kDT2 * wav[t];

        float keep0, keep1;   // running values handed from outer row to interior

        // ---- phase 1: the CTA's outer row (the only rows neighbors read) ----
        if (active) {
            if (g == 0) {
                // slab row 0: needs prev CTA's last row (remote)
                float halo = prevCur[(kRows - 1) * kNX + c];
                float c0   = cb[0];
                float cp1  = cb[kNX];
                float lap  = ((halo + cp1) + (cb[-1] + cb[1]) - 4.0f * c0) * kInvDH2;
                float hn   = fmaf(c2[0], lap, 2.0f * c0 - h2[0]);
                if (isSrcCol && srcRow == 0) hn += inj;
                h2[0] = c0;
                if (!skipFirst) nb[0] = hn;
                keep0 = c0;  keep1 = cp1;          // row0, row1 values
            } else {
                // slab row kRows-1 (local idx kHalf-1): needs next CTA's row 0 (remote)
                constexpr int L = kHalf - 1;
                float halo = nextCur[c];
                float c0   = cb[L * kNX];
                float cm1  = cb[(L - 1) * kNX];
                float lap  = ((cm1 + halo) + (cb[L * kNX - 1] + cb[L * kNX + 1]) - 4.0f * c0) * kInvDH2;
                float hn   = fmaf(c2[L], lap, 2.0f * c0 - h2[L]);
                if (isSrcCol && srcRow == L) hn += inj;
                h2[L] = c0;
                if (!skipLast) nb[L * kNX] = hn;
                keep0 = c0;  keep1 = cm1;          // rowL, rowL-1 values
            }
        }

        // ---- publish outer rows; barrier latency overlaps interior compute ----
        CLUSTER_ARRIVE();

        // ---- phase 2: interior rows (read by nobody outside this CTA) ----
        if (active) {
            if (g == 0) {
                float cm1 = keep0, c0 = keep1;     // rows 0,1
#pragma unroll
                for (int i = 1; i < kHalf; i++) {
                    float cp1 = cb[(i + 1) * kNX]; // i=kHalf-1 -> g=1's first row (local)
                    float l   = cb[i * kNX - 1];
                    float r   = cb[i * kNX + 1];
                    float lap = ((cm1 + cp1) + (l + r) - 4.0f * c0) * kInvDH2;
                    float hn  = fmaf(c2[i], lap, 2.0f * c0 - h2[i]);
                    if (isSrcCol && srcRow == i) hn += inj;
                    h2[i] = c0;
                    nb[i * kNX] = hn;
                    cm1 = c0; c0 = cp1;
                }
            } else {
                float cp1 = keep0, c0 = keep1;     // rows L, L-1
#pragma unroll
                for (int i = kHalf - 2; i >= 0; i--) {
                    float cm1 = (i > 0) ? cb[(i - 1) * kNX] : cb[-kNX]; // i=0 -> g=0's last row
                    float l   = cb[i * kNX - 1];
                    float r   = cb[i * kNX + 1];
                    float lap = ((cm1 + cp1) + (l + r) - 4.0f * c0) * kInvDH2;
                    float hn  = fmaf(c2[i], lap, 2.0f * c0 - h2[i]);
                    if (isSrcCol && srcRow == i) hn += inj;
                    h2[i] = c0;
                    nb[i * kNX] = hn;
                    cp1 = c0; c0 = cm1;
                }
            }
        }

        __syncthreads();     // intra-CTA: all of nxt visible to all threads

        // receiver gather (own-CTA smem only) overlaps remaining barrier skew
        if (tid < cnt)
            out[(batch * kNT + t) * kNREC + recK[tid]] = nxt[recOff[tid]];

        CLUSTER_WAIT();      // acquire: neighbors' outer rows of step t visible
    }
}

extern "C" void kernel_launch(void* const* d_in, const int* in_sizes, int n_in,
                              void* d_out, int out_size)
{
    (void)in_sizes; (void)n_in; (void)out_size;
    const float* x   = (const float*)d_in[0];
    const float* vp  = (const float*)d_in[1];
    const int*   src = (const int*)d_in[2];
    const int*   rec = (const int*)d_in[3];
    float*       out = (float*)d_out;

    cudaFuncSetAttribute(wave_fd_kernel<16>,
                         cudaFuncAttributeMaxDynamicSharedMemorySize, smem_bytes(16));
    cudaFuncSetAttribute(wave_fd_kernel<16>,
                         cudaFuncAttributeNonPortableClusterSizeAllowed, 1);
    cudaFuncSetAttribute(wave_fd_kernel<8>,
                         cudaFuncAttributeMaxDynamicSharedMemorySize, smem_bytes(8));

    int maxCluster = 0;
    {
        cudaLaunchConfig_t probe = {};
        probe.gridDim          = dim3(kB * 16, 1, 1);
        probe.blockDim         = dim3(kThreads, 1, 1);
        probe.dynamicSmemBytes = smem_bytes(16);
        cudaOccupancyMaxPotentialClusterSize(&maxCluster, (const void*)wave_fd_kernel<16>, &probe);
    }

    cudaLaunchAttribute attr[1];
    attr[0].id = cudaLaunchAttributeClusterDimension;
    attr[0].val.clusterDim.y = 1;
    attr[0].val.clusterDim.z = 1;

    cudaLaunchConfig_t cfg = {};
    cfg.blockDim = dim3(kThreads, 1, 1);
    cfg.stream   = 0;
    cfg.attrs    = attr;
    cfg.numAttrs = 1;

    if (maxCluster >= 16) {
        cfg.gridDim              = dim3(kB * 16, 1, 1);
        cfg.dynamicSmemBytes     = smem_bytes(16);
        attr[0].val.clusterDim.x = 16;
        cudaLaunchKernelEx(&cfg, wave_fd_kernel<16>, x, vp, src, rec, out);
    } else {
        cfg.gridDim              = dim3(kB * 8, 1, 1);
        cfg.dynamicSmemBytes     = smem_bytes(8);
        attr[0].val.clusterDim.x = 8;
        cudaLaunchKernelEx(&cfg, wave_fd_kernel<8>, x, vp, src, rec, out);
    }
}